// round 9
// baseline (speedup 1.0000x reference)
#include <cuda_runtime.h>
#include <cuda_fp16.h>
#include <cstdint>

#define BB   128
#define SSEQ 513
#define HH   256
#define SSH  (SSEQ * HH)

#define NX   (BB * SSEQ * HH)
#define NX8  (NX / 8)
#define NW   (5 * HH * HH)
#define NW8  (NW / 8)
#define NCVT (NX8 + NW8 + 32)

__device__ __half gx[NX];            // [b][s][h]  (same layout as x, just fp16)
__device__ __half gw[NW];            // [widx][n][h]
__device__ float  gbsum[HH];

// ---------------- GEMM tiling: k=64 stages, 2-stage ring, 1 barrier/tile ----
#define KT    64
#define NKT   4
#define ROWB  144                    // 64 fp16 = 128B + 16B pad (ldmatrix conflict-free)
#define TILEB (128 * ROWB)           // 18432
#define STAGE (2 * TILEB)            // 36864
#define SMTOT (2 * STAGE)            // 73728

__device__ __forceinline__ uint32_t smem_u32(const void* p) {
    uint32_t a;
    asm("{ .reg .u64 t; cvta.to.shared.u64 t, %1; cvt.u32.u64 %0, t; }" : "=r"(a) : "l"(p));
    return a;
}
__device__ __forceinline__ void cpasync16(uint32_t dst, const void* src) {
    asm volatile("cp.async.cg.shared.global [%0], [%1], 16;" :: "r"(dst), "l"(src));
}
__device__ __forceinline__ void cp_commit() { asm volatile("cp.async.commit_group;"); }
__device__ __forceinline__ void cp_wait0()  { asm volatile("cp.async.wait_group 0;"); }
__device__ __forceinline__ void ldsm_x4(uint32_t* r, uint32_t addr) {
    asm volatile("ldmatrix.sync.aligned.m8n8.x4.shared.b16 {%0,%1,%2,%3}, [%4];"
                 : "=r"(r[0]), "=r"(r[1]), "=r"(r[2]), "=r"(r[3]) : "r"(addr));
}
__device__ __forceinline__ void mma_f16(float* d, const uint32_t* a, uint32_t b0, uint32_t b1) {
    asm volatile(
        "mma.sync.aligned.m16n8k16.row.col.f32.f16.f16.f32 "
        "{%0,%1,%2,%3}, {%4,%5,%6,%7}, {%8,%9}, {%0,%1,%2,%3};"
        : "+f"(d[0]), "+f"(d[1]), "+f"(d[2]), "+f"(d[3])
        : "r"(a[0]), "r"(a[1]), "r"(a[2]), "r"(a[3]), "r"(b0), "r"(b1));
}
__device__ __forceinline__ uint2 f4_to_h4(float4 v) {
    __half2 h0 = __floats2half2_rn(v.x, v.y);
    __half2 h1 = __floats2half2_rn(v.z, v.w);
    uint2 u;
    u.x = *reinterpret_cast<uint32_t*>(&h0);
    u.y = *reinterpret_cast<uint32_t*>(&h1);
    return u;
}

// ---- kernel 1: straight fp32 -> fp16 (no transpose; fully coalesced both sides) ----
__global__ __launch_bounds__(256)
void cvt_kernel(const float* __restrict__ x,
                const float* __restrict__ W,
                const float* __restrict__ bias)
{
    const uint32_t id = blockIdx.x * 256 + threadIdx.x;
    if (id < NX8) {
        const size_t f = (size_t)id * 8;
        float4 v0 = *reinterpret_cast<const float4*>(x + f);
        float4 v1 = *reinterpret_cast<const float4*>(x + f + 4);
        uint4 o;
        uint2 a = f4_to_h4(v0), c = f4_to_h4(v1);
        o.x = a.x; o.y = a.y; o.z = c.x; o.w = c.y;
        *reinterpret_cast<uint4*>(&gx[f]) = o;
    } else if (id < NX8 + NW8) {
        const size_t f = (size_t)(id - NX8) * 8;
        float4 v0 = *reinterpret_cast<const float4*>(W + f);
        float4 v1 = *reinterpret_cast<const float4*>(W + f + 4);
        uint4 o;
        uint2 a = f4_to_h4(v0), c = f4_to_h4(v1);
        o.x = a.x; o.y = a.y; o.z = c.x; o.w = c.y;
        *reinterpret_cast<uint4*>(&gw[f]) = o;
    } else if (id < NCVT) {
        const int t = (int)(id - NX8 - NW8);
        #pragma unroll
        for (int j = 0; j < 8; ++j) {
            const int c = t * 8 + j;
            float v = 0.0f;
            #pragma unroll
            for (int l = 0; l < 5; ++l) v += bias[l * HH + c];
            gbsum[c] = v;
        }
    }
}

// ---- kernel 2: fp16 GEMM, k=64 stages, single barrier per tile ----
// CTA (n-half, s): out[0:128, s, n0:n0+128] = x[:,s,:] @ W[idx]^T + bsum
__global__ __launch_bounds__(256, 2)
void pmha_f16_k64_kernel(float* __restrict__ out)
{
    extern __shared__ char smem[];
    const uint32_t sb = smem_u32(smem);
    const int tid  = threadIdx.x;
    const int lane = tid & 31;
    const int wid  = tid >> 5;
    const int tg   = lane >> 2;
    const int tig  = lane & 3;
    const int wm   = (wid >> 2) * 64;
    const int wn   = (wid & 3) * 32;
    const int s    = blockIdx.y;
    const int n0   = blockIdx.x * 128;
    const int widx = (s < 3) ? s : ((s & 1) ? 3 : 4);

    const __half* xs = gx + (size_t)s * HH;                       // row b at +b*SSH
    const __half* Wp = gw + (size_t)widx * (HH * HH) + (size_t)n0 * HH;

    const int prow = tid >> 3;        // 0..31 (x4 steps of 32)
    const int pc   = tid & 7;         // 16B chunk 0..7

    auto prefetch = [&](int kt) {
        const int k0 = kt * KT;
        const uint32_t base = sb + (kt & 1) * STAGE;
        #pragma unroll
        for (int t = 0; t < 4; ++t) {
            const int row = prow + t * 32;
            const uint32_t off = (uint32_t)row * ROWB + (uint32_t)pc * 16;
            cpasync16(base + off,         xs + (size_t)row * SSH + k0 + pc * 8);
            cpasync16(base + TILEB + off, Wp + (size_t)row * HH + k0 + pc * 8);
        }
    };

    prefetch(0); cp_commit();

    const int lr = lane & 15;
    const int lc = lane >> 4;
    uint32_t aA[4], aB[2];
    #pragma unroll
    for (int i = 0; i < 4; ++i)
        aA[i] = sb + (uint32_t)(wm + i * 16 + lr) * ROWB + lc * 16;
    #pragma unroll
    for (int jj = 0; jj < 2; ++jj)
        aB[jj] = sb + TILEB + (uint32_t)(wn + jj * 16 + lr) * ROWB + lc * 16;

    float acc[4][4][4] = {};

    for (int kt = 0; kt < NKT; ++kt) {
        cp_wait0();
        __syncthreads();

        if (kt + 1 < NKT) { prefetch(kt + 1); cp_commit(); }

        const uint32_t stoff = (kt & 1) * STAGE;
        #pragma unroll
        for (int ks = 0; ks < 4; ++ks) {
            const uint32_t off = stoff + ks * 32;
            uint32_t b[2][4];
            ldsm_x4(b[0], aB[0] + off);
            ldsm_x4(b[1], aB[1] + off);
            uint32_t a0[4], a1[4];
            ldsm_x4(a0, aA[0] + off);
            #pragma unroll
            for (int i = 0; i < 4; ++i) {
                uint32_t* ac = (i & 1) ? a1 : a0;
                uint32_t* an = (i & 1) ? a0 : a1;
                if (i < 3) ldsm_x4(an, aA[i + 1] + off);   // prefetch next A row
                #pragma unroll
                for (int j = 0; j < 4; ++j) {
                    const int jj = j >> 1, sel = j & 1;
                    mma_f16(acc[i][j], ac, b[jj][sel], b[jj][sel + 2]);
                }
            }
        }
    }

    // epilogue: + bias (L2-hot), float2 stores
    #pragma unroll
    for (int i = 0; i < 4; ++i) {
        const int r0 = wm + i * 16 + tg;
        float* o0 = out + (size_t)r0 * SSH + (size_t)s * HH + n0;
        float* o1 = o0 + (size_t)8 * SSH;
        #pragma unroll
        for (int j = 0; j < 4; ++j) {
            const int c = wn + j * 8 + 2 * tig;
            const float b0v = gbsum[n0 + c], b1v = gbsum[n0 + c + 1];
            float2 v0 = make_float2(acc[i][j][0] + b0v, acc[i][j][1] + b1v);
            float2 v1 = make_float2(acc[i][j][2] + b0v, acc[i][j][3] + b1v);
            *reinterpret_cast<float2*>(o0 + c) = v0;
            *reinterpret_cast<float2*>(o1 + c) = v1;
        }
    }
}

extern "C" void kernel_launch(void* const* d_in, const int* in_sizes, int n_in,
                              void* d_out, int out_size)
{
    const float* x    = (const float*)d_in[0];   // [128, 513, 256]
    const float* W    = (const float*)d_in[1];   // [5, 256, 256]
    const float* bias = (const float*)d_in[2];   // [5, 256]
    float* out        = (float*)d_out;           // [128, 513, 4, 64]

    cvt_kernel<<<(NCVT + 255) / 256, 256>>>(x, W, bias);

    cudaFuncSetAttribute(pmha_f16_k64_kernel, cudaFuncAttributeMaxDynamicSharedMemorySize, SMTOT);
    dim3 grid(2, SSEQ);
    pmha_f16_k64_kernel<<<grid, 256, SMTOT>>>(out);
}

// round 10
// speedup vs baseline: 1.2926x; 1.2926x over previous
#include <cuda_runtime.h>
#include <cuda_fp16.h>
#include <cstdint>

#define BB   128
#define SSEQ 513
#define HH   256
#define SSH  (SSEQ * HH)
#define SBH  (BB * HH)               // 32768: gx row-block per s

#define NX   (BB * SSEQ * HH)
#define NX8  (NX / 8)
#define NW   (5 * HH * HH)
#define NW8  (NW / 8)
#define NCVT (NX8 + NW8 + 32)

__device__ __half gx[NX];            // [s][b][h]  (transposed: contiguous 32KB block per s)
__device__ __half gw[NW];            // [widx][n][h]
__device__ float  gbsum[HH];

// ---------------- GEMM tiling: k=64 stages, 2-stage ring, 1 barrier/tile ----
#define KT    64
#define NKT   4
#define ROWB  144                    // 64 fp16 = 128B + 16B pad (ldmatrix conflict-free)
#define TILEB (128 * ROWB)           // 18432
#define STAGE (2 * TILEB)            // 36864
#define SMTOT (2 * STAGE)            // 73728

__device__ __forceinline__ uint32_t smem_u32(const void* p) {
    uint32_t a;
    asm("{ .reg .u64 t; cvta.to.shared.u64 t, %1; cvt.u32.u64 %0, t; }" : "=r"(a) : "l"(p));
    return a;
}
__device__ __forceinline__ void cpasync16(uint32_t dst, const void* src) {
    asm volatile("cp.async.cg.shared.global [%0], [%1], 16;" :: "r"(dst), "l"(src));
}
__device__ __forceinline__ void cp_commit() { asm volatile("cp.async.commit_group;"); }
__device__ __forceinline__ void cp_wait0()  { asm volatile("cp.async.wait_group 0;"); }
__device__ __forceinline__ void ldsm_x4(uint32_t* r, uint32_t addr) {
    asm volatile("ldmatrix.sync.aligned.m8n8.x4.shared.b16 {%0,%1,%2,%3}, [%4];"
                 : "=r"(r[0]), "=r"(r[1]), "=r"(r[2]), "=r"(r[3]) : "r"(addr));
}
__device__ __forceinline__ void mma_f16(float* d, const uint32_t* a, uint32_t b0, uint32_t b1) {
    asm volatile(
        "mma.sync.aligned.m16n8k16.row.col.f32.f16.f16.f32 "
        "{%0,%1,%2,%3}, {%4,%5,%6,%7}, {%8,%9}, {%0,%1,%2,%3};"
        : "+f"(d[0]), "+f"(d[1]), "+f"(d[2]), "+f"(d[3])
        : "r"(a[0]), "r"(a[1]), "r"(a[2]), "r"(a[3]), "r"(b0), "r"(b1));
}
__device__ __forceinline__ uint2 f4_to_h4(float4 v) {
    __half2 h0 = __floats2half2_rn(v.x, v.y);
    __half2 h1 = __floats2half2_rn(v.z, v.w);
    uint2 u;
    u.x = *reinterpret_cast<uint32_t*>(&h0);
    u.y = *reinterpret_cast<uint32_t*>(&h1);
    return u;
}

// ---- kernel 1: fp32 -> fp16 + x transpose to [s][b][h] + bias presum ----
// (warp covers h=0..255 for one (b,s): reads AND writes are 512B-contiguous per warp)
__global__ __launch_bounds__(256)
void cvt_kernel(const float* __restrict__ x,
                const float* __restrict__ W,
                const float* __restrict__ bias)
{
    const uint32_t id = blockIdx.x * 256 + threadIdx.x;
    if (id < NX8) {
        const size_t f = (size_t)id * 8;
        const int b   = (int)(f / (SSEQ * HH));
        const int rem = (int)(f % (SSEQ * HH));
        const int s   = rem / HH;
        const int h   = rem % HH;
        float4 v0 = *reinterpret_cast<const float4*>(x + f);
        float4 v1 = *reinterpret_cast<const float4*>(x + f + 4);
        uint4 o;
        uint2 a = f4_to_h4(v0), c = f4_to_h4(v1);
        o.x = a.x; o.y = a.y; o.z = c.x; o.w = c.y;
        *reinterpret_cast<uint4*>(&gx[(size_t)s * SBH + (size_t)b * HH + h]) = o;
    } else if (id < NX8 + NW8) {
        const size_t f = (size_t)(id - NX8) * 8;
        float4 v0 = *reinterpret_cast<const float4*>(W + f);
        float4 v1 = *reinterpret_cast<const float4*>(W + f + 4);
        uint4 o;
        uint2 a = f4_to_h4(v0), c = f4_to_h4(v1);
        o.x = a.x; o.y = a.y; o.z = c.x; o.w = c.y;
        *reinterpret_cast<uint4*>(&gw[f]) = o;
    } else if (id < NCVT) {
        const int t = (int)(id - NX8 - NW8);
        #pragma unroll
        for (int j = 0; j < 8; ++j) {
            const int c = t * 8 + j;
            float v = 0.0f;
            #pragma unroll
            for (int l = 0; l < 5; ++l) v += bias[l * HH + c];
            gbsum[c] = v;
        }
    }
}

// ---- kernel 2: fp16 GEMM, k=64 stages, single barrier per tile ----
// CTA (n-half, s): out[0:128, s, n0:n0+128] = x_s @ W[idx]^T + bsum
__global__ __launch_bounds__(256, 2)
void pmha_f16_k64_kernel(float* __restrict__ out)
{
    extern __shared__ char smem[];
    const uint32_t sb = smem_u32(smem);
    const int tid  = threadIdx.x;
    const int lane = tid & 31;
    const int wid  = tid >> 5;
    const int tg   = lane >> 2;
    const int tig  = lane & 3;
    const int wm   = (wid >> 2) * 64;
    const int wn   = (wid & 3) * 32;
    const int s    = blockIdx.y;
    const int n0   = blockIdx.x * 128;
    const int widx = (s < 3) ? s : ((s & 1) ? 3 : 4);

    const __half* xs = gx + (size_t)s * SBH;                      // contiguous 128x256 block
    const __half* Wp = gw + (size_t)widx * (HH * HH) + (size_t)n0 * HH;

    const int prow = tid >> 3;        // 0..31 (x4 steps of 32)
    const int pc   = tid & 7;         // 16B chunk 0..7

    auto prefetch = [&](int kt) {
        const int k0 = kt * KT;
        const uint32_t base = sb + (kt & 1) * STAGE;
        #pragma unroll
        for (int t = 0; t < 4; ++t) {
            const int row = prow + t * 32;
            const uint32_t off = (uint32_t)row * ROWB + (uint32_t)pc * 16;
            cpasync16(base + off,         xs + (size_t)row * HH + k0 + pc * 8);
            cpasync16(base + TILEB + off, Wp + (size_t)row * HH + k0 + pc * 8);
        }
    };

    prefetch(0); cp_commit();

    const int lr = lane & 15;
    const int lc = lane >> 4;
    uint32_t aA[4], aB[2];
    #pragma unroll
    for (int i = 0; i < 4; ++i)
        aA[i] = sb + (uint32_t)(wm + i * 16 + lr) * ROWB + lc * 16;
    #pragma unroll
    for (int jj = 0; jj < 2; ++jj)
        aB[jj] = sb + TILEB + (uint32_t)(wn + jj * 16 + lr) * ROWB + lc * 16;

    float acc[4][4][4] = {};

    for (int kt = 0; kt < NKT; ++kt) {
        cp_wait0();
        __syncthreads();

        if (kt + 1 < NKT) { prefetch(kt + 1); cp_commit(); }

        const uint32_t stoff = (kt & 1) * STAGE;
        #pragma unroll
        for (int ks = 0; ks < 4; ++ks) {
            const uint32_t off = stoff + ks * 32;   // 16 fp16 = 32B per k16 step
            uint32_t a[4][4], b[2][4];
            #pragma unroll
            for (int i = 0; i < 4; ++i) ldsm_x4(a[i], aA[i] + off);
            #pragma unroll
            for (int jj = 0; jj < 2; ++jj) ldsm_x4(b[jj], aB[jj] + off);
            #pragma unroll
            for (int i = 0; i < 4; ++i)
                #pragma unroll
                for (int j = 0; j < 4; ++j) {
                    const int jj = j >> 1, sel = j & 1;
                    mma_f16(acc[i][j], a[i], b[jj][sel], b[jj][sel + 2]);
                }
        }
    }

    // epilogue: bias cached in registers, float2 stores
    float bA[4], bB[4];
    #pragma unroll
    for (int j = 0; j < 4; ++j) {
        const int c = wn + j * 8 + 2 * tig;
        bA[j] = gbsum[n0 + c];
        bB[j] = gbsum[n0 + c + 1];
    }
    #pragma unroll
    for (int i = 0; i < 4; ++i) {
        const int r0 = wm + i * 16 + tg;
        float* o0 = out + (size_t)r0 * SSH + (size_t)s * HH + n0;
        float* o1 = o0 + (size_t)8 * SSH;
        #pragma unroll
        for (int j = 0; j < 4; ++j) {
            const int c = wn + j * 8 + 2 * tig;
            float2 v0 = make_float2(acc[i][j][0] + bA[j], acc[i][j][1] + bB[j]);
            float2 v1 = make_float2(acc[i][j][2] + bA[j], acc[i][j][3] + bB[j]);
            *reinterpret_cast<float2*>(o0 + c) = v0;
            *reinterpret_cast<float2*>(o1 + c) = v1;
        }
    }
}

extern "C" void kernel_launch(void* const* d_in, const int* in_sizes, int n_in,
                              void* d_out, int out_size)
{
    const float* x    = (const float*)d_in[0];   // [128, 513, 256]
    const float* W    = (const float*)d_in[1];   // [5, 256, 256]
    const float* bias = (const float*)d_in[2];   // [5, 256]
    float* out        = (float*)d_out;           // [128, 513, 4, 64]

    cvt_kernel<<<(NCVT + 255) / 256, 256>>>(x, W, bias);

    cudaFuncSetAttribute(pmha_f16_k64_kernel, cudaFuncAttributeMaxDynamicSharedMemorySize, SMTOT);
    dim3 grid(2, SSEQ);
    pmha_f16_k64_kernel<<<grid, 256, SMTOT>>>(out);
}

// round 11
// speedup vs baseline: 1.3374x; 1.0346x over previous
#include <cuda_runtime.h>
#include <cuda_fp16.h>
#include <cstdint>

#define BB   128
#define SSEQ 513
#define HH   256
#define SSH  (SSEQ * HH)
#define SBH  (BB * HH)               // 32768: gx row-block per s

#define NX    (BB * SSEQ * HH)
#define NX16  (NX / 16)              // 1,050,624
#define NW    (5 * HH * HH)
#define NW16  (NW / 16)              // 20,480
#define NCVT  (NX16 + NW16 + 32)

__device__ __half gx[NX];            // [s][b][h]  (transposed: contiguous 32KB block per s)
__device__ __half gw[NW];            // [widx][n][h]
__device__ float  gbsum[HH];

// ---------------- GEMM tiling: k=64 stages, 2-stage ring, 1 barrier/tile ----
#define KT    64
#define NKT   4
#define ROWB  144                    // 64 fp16 = 128B + 16B pad (ldmatrix conflict-free)
#define TILEB (128 * ROWB)           // 18432
#define STAGE (2 * TILEB)            // 36864
#define SMTOT (2 * STAGE)            // 73728

__device__ __forceinline__ uint32_t smem_u32(const void* p) {
    uint32_t a;
    asm("{ .reg .u64 t; cvta.to.shared.u64 t, %1; cvt.u32.u64 %0, t; }" : "=r"(a) : "l"(p));
    return a;
}
__device__ __forceinline__ void cpasync16(uint32_t dst, const void* src) {
    asm volatile("cp.async.ca.shared.global [%0], [%1], 16;" :: "r"(dst), "l"(src));
}
__device__ __forceinline__ void cp_commit() { asm volatile("cp.async.commit_group;"); }
__device__ __forceinline__ void cp_wait0()  { asm volatile("cp.async.wait_group 0;"); }
__device__ __forceinline__ void ldsm_x4(uint32_t* r, uint32_t addr) {
    asm volatile("ldmatrix.sync.aligned.m8n8.x4.shared.b16 {%0,%1,%2,%3}, [%4];"
                 : "=r"(r[0]), "=r"(r[1]), "=r"(r[2]), "=r"(r[3]) : "r"(addr));
}
__device__ __forceinline__ void mma_f16(float* d, const uint32_t* a, uint32_t b0, uint32_t b1) {
    asm volatile(
        "mma.sync.aligned.m16n8k16.row.col.f32.f16.f16.f32 "
        "{%0,%1,%2,%3}, {%4,%5,%6,%7}, {%8,%9}, {%0,%1,%2,%3};"
        : "+f"(d[0]), "+f"(d[1]), "+f"(d[2]), "+f"(d[3])
        : "r"(a[0]), "r"(a[1]), "r"(a[2]), "r"(a[3]), "r"(b0), "r"(b1));
}
__device__ __forceinline__ uint2 f4_to_h4(float4 v) {
    __half2 h0 = __floats2half2_rn(v.x, v.y);
    __half2 h1 = __floats2half2_rn(v.z, v.w);
    uint2 u;
    u.x = *reinterpret_cast<uint32_t*>(&h0);
    u.y = *reinterpret_cast<uint32_t*>(&h1);
    return u;
}
__device__ __forceinline__ uint4 f8_to_h8(float4 v0, float4 v1) {
    uint2 a = f4_to_h4(v0), c = f4_to_h4(v1);
    uint4 o; o.x = a.x; o.y = a.y; o.z = c.x; o.w = c.y;
    return o;
}

// ---- kernel 1: fp32 -> fp16 + x transpose to [s][b][h] + bias presum ----
// 16 elements per thread: 2 independent 32B reads, 2x16B writes (MLP=4)
__global__ __launch_bounds__(256)
void cvt_kernel(const float* __restrict__ x,
                const float* __restrict__ W,
                const float* __restrict__ bias)
{
    const uint32_t id = blockIdx.x * 256 + threadIdx.x;
    if (id < NX16) {
        const size_t f = (size_t)id * 16;
        const int b   = (int)(f / (SSEQ * HH));
        const int rem = (int)(f % (SSEQ * HH));
        const int s   = rem / HH;
        const int h   = rem % HH;
        const float4* xp = reinterpret_cast<const float4*>(x + f);
        float4 v0 = xp[0], v1 = xp[1], v2 = xp[2], v3 = xp[3];
        uint4* op = reinterpret_cast<uint4*>(&gx[(size_t)s * SBH + (size_t)b * HH + h]);
        op[0] = f8_to_h8(v0, v1);
        op[1] = f8_to_h8(v2, v3);
    } else if (id < NX16 + NW16) {
        const size_t f = (size_t)(id - NX16) * 16;
        const float4* wp = reinterpret_cast<const float4*>(W + f);
        float4 v0 = wp[0], v1 = wp[1], v2 = wp[2], v3 = wp[3];
        uint4* op = reinterpret_cast<uint4*>(&gw[f]);
        op[0] = f8_to_h8(v0, v1);
        op[1] = f8_to_h8(v2, v3);
    } else if (id < NCVT) {
        const int t = (int)(id - NX16 - NW16);
        #pragma unroll
        for (int j = 0; j < 8; ++j) {
            const int c = t * 8 + j;
            float v = 0.0f;
            #pragma unroll
            for (int l = 0; l < 5; ++l) v += bias[l * HH + c];
            gbsum[c] = v;
        }
    }
}

// ---- kernel 2: fp16 GEMM, k=64 stages, single barrier per tile (round-8 config) ----
// CTA (n-half, s): out[0:128, s, n0:n0+128] = x_s @ W[idx]^T + bsum
__global__ __launch_bounds__(256, 2)
void pmha_f16_k64_kernel(float* __restrict__ out)
{
    extern __shared__ char smem[];
    const uint32_t sb = smem_u32(smem);
    const int tid  = threadIdx.x;
    const int lane = tid & 31;
    const int wid  = tid >> 5;
    const int tg   = lane >> 2;
    const int tig  = lane & 3;
    const int wm   = (wid >> 2) * 64;
    const int wn   = (wid & 3) * 32;
    const int s    = blockIdx.y;
    const int n0   = blockIdx.x * 128;
    const int widx = (s < 3) ? s : ((s & 1) ? 3 : 4);

    const __half* xs = gx + (size_t)s * SBH;                      // contiguous 128x256 block
    const __half* Wp = gw + (size_t)widx * (HH * HH) + (size_t)n0 * HH;

    const int prow = tid >> 3;        // 0..31 (x4 steps of 32)
    const int pc   = tid & 7;         // 16B chunk 0..7

    auto prefetch = [&](int kt) {
        const int k0 = kt * KT;
        const uint32_t base = sb + (kt & 1) * STAGE;
        #pragma unroll
        for (int t = 0; t < 4; ++t) {
            const int row = prow + t * 32;
            const uint32_t off = (uint32_t)row * ROWB + (uint32_t)pc * 16;
            cpasync16(base + off,         xs + (size_t)row * HH + k0 + pc * 8);
            cpasync16(base + TILEB + off, Wp + (size_t)row * HH + k0 + pc * 8);
        }
    };

    prefetch(0); cp_commit();

    const int lr = lane & 15;
    const int lc = lane >> 4;
    uint32_t aA[4], aB[2];
    #pragma unroll
    for (int i = 0; i < 4; ++i)
        aA[i] = sb + (uint32_t)(wm + i * 16 + lr) * ROWB + lc * 16;
    #pragma unroll
    for (int jj = 0; jj < 2; ++jj)
        aB[jj] = sb + TILEB + (uint32_t)(wn + jj * 16 + lr) * ROWB + lc * 16;

    float acc[4][4][4] = {};

    for (int kt = 0; kt < NKT; ++kt) {
        cp_wait0();
        __syncthreads();

        if (kt + 1 < NKT) { prefetch(kt + 1); cp_commit(); }

        const uint32_t stoff = (kt & 1) * STAGE;
        #pragma unroll
        for (int ks = 0; ks < 4; ++ks) {
            const uint32_t off = stoff + ks * 32;   // 16 fp16 = 32B per k16 step
            uint32_t a[4][4], b[2][4];
            #pragma unroll
            for (int i = 0; i < 4; ++i) ldsm_x4(a[i], aA[i] + off);
            #pragma unroll
            for (int jj = 0; jj < 2; ++jj) ldsm_x4(b[jj], aB[jj] + off);
            #pragma unroll
            for (int i = 0; i < 4; ++i)
                #pragma unroll
                for (int j = 0; j < 4; ++j) {
                    const int jj = j >> 1, sel = j & 1;
                    mma_f16(acc[i][j], a[i], b[jj][sel], b[jj][sel + 2]);
                }
        }
    }

    // epilogue: bias cached in registers, float2 stores
    float bA[4], bB[4];
    #pragma unroll
    for (int j = 0; j < 4; ++j) {
        const int c = wn + j * 8 + 2 * tig;
        bA[j] = gbsum[n0 + c];
        bB[j] = gbsum[n0 + c + 1];
    }
    #pragma unroll
    for (int i = 0; i < 4; ++i) {
        const int r0 = wm + i * 16 + tg;
        float* o0 = out + (size_t)r0 * SSH + (size_t)s * HH + n0;
        float* o1 = o0 + (size_t)8 * SSH;
        #pragma unroll
        for (int j = 0; j < 4; ++j) {
            const int c = wn + j * 8 + 2 * tig;
            float2 v0 = make_float2(acc[i][j][0] + bA[j], acc[i][j][1] + bB[j]);
            float2 v1 = make_float2(acc[i][j][2] + bA[j], acc[i][j][3] + bB[j]);
            *reinterpret_cast<float2*>(o0 + c) = v0;
            *reinterpret_cast<float2*>(o1 + c) = v1;
        }
    }
}

extern "C" void kernel_launch(void* const* d_in, const int* in_sizes, int n_in,
                              void* d_out, int out_size)
{
    const float* x    = (const float*)d_in[0];   // [128, 513, 256]
    const float* W    = (const float*)d_in[1];   // [5, 256, 256]
    const float* bias = (const float*)d_in[2];   // [5, 256]
    float* out        = (float*)d_out;           // [128, 513, 4, 64]

    cvt_kernel<<<(NCVT + 255) / 256, 256>>>(x, W, bias);

    cudaFuncSetAttribute(pmha_f16_k64_kernel, cudaFuncAttributeMaxDynamicSharedMemorySize, SMTOT);
    dim3 grid(2, SSEQ);
    pmha_f16_k64_kernel<<<grid, 256, SMTOT>>>(out);
}